// round 5
// baseline (speedup 1.0000x reference)
#include <cuda_runtime.h>
#include <cstdint>

// ---------------------------------------------------------------------------
// TDGSPooling2d: hard Gumbel-softmax 2x2 pooling (K=2, stride 2).
// out = x[argmax over patch of (x/temp_relu_eps + gumbel)]
// gumbel bits: JAX threefry2x32, key=(0,42), partitionable (bits = o0^o1 of
// threefry(hi=0, lo=flat_index)).
// Pipe balancing: threefry adds forced to IMAD (fma pipe) via mad.lo.u32
// with opaque runtime 'one'; round-1 add elided (x0 starts at 0); uniform
// built via umulhi+I2F+FFMA (no alu shift/or). Fast gumbel via MUFU.LG2
// with certified error bound + NaN-safe clamp; precise (IEEE div +
// libdevice logf) fallback when the argmax margin is unsafe.
// 3D grid: no integer divisions anywhere. 2 outputs/thread, 8-way hash ILP.
// ---------------------------------------------------------------------------

constexpr int B  = 32;
constexpr int C  = 128;
constexpr int H  = 112;
constexpr int W  = 112;
constexpr int Ho = 56;
constexpr int Wo = 56;
constexpr int P   = C * Ho * Wo;   // 401408
constexpr int XPB = C * H * W;     // 1605632

__device__ __forceinline__ unsigned rotl32(unsigned x, int r) {
    return __funnelshift_l(x, x, r);          // SHF (alu)
}

// d = a*one + c  -> IMAD on the fma pipe ('one' is an opaque runtime 1)
__device__ __forceinline__ unsigned mad1(unsigned a, unsigned one, unsigned c) {
    unsigned d;
    asm("mad.lo.u32 %0, %1, %2, %3;" : "=r"(d) : "r"(a), "r"(one), "r"(c));
    return d;
}
// d = one*imm + c  -> IMAD (imm multiplier) on the fma pipe
#define MAD1I(one, imm, c) ({                                   \
    unsigned d_;                                                \
    asm("mad.lo.u32 %0, %1, %2, %3;"                            \
        : "=r"(d_) : "r"(one), "n"(imm), "r"(c));               \
    d_; })

// Threefry-2x32, 20 rounds, key=(0,42), constants folded, fold o0^o1.
// Entry e must equal counter + 42 (first key injection pre-applied).
// Round 1 elided: initial x0 = 0 so x0_after_add = e.
__device__ __forceinline__ unsigned tf_fold_entry(unsigned e, unsigned one) {
    const unsigned ks1 = 42u;
    const unsigned ks2 = 0x1BD11BDAu ^ 42u;
    unsigned x0 = e;
    unsigned x1 = rotl32(e, 13) ^ e;
#define TF_R(r) { x0 = mad1(x1, one, x0); x1 = rotl32(x1, (r)); x1 ^= x0; }
    TF_R(15) TF_R(26) TF_R(6)
    x0 = MAD1I(one, ks1, x0);        x1 = MAD1I(one, (ks2 + 1u), x1);
    TF_R(17) TF_R(29) TF_R(16) TF_R(24)
    x0 = MAD1I(one, ks2, x0);        x1 = MAD1I(one, 2u, x1);
    TF_R(13) TF_R(15) TF_R(26) TF_R(6)
    /* x0 += 0 */                    x1 = MAD1I(one, (ks1 + 3u), x1);
    TF_R(17) TF_R(29) TF_R(16) TF_R(24)
    x0 = MAD1I(one, ks1, x0);        x1 = MAD1I(one, (ks2 + 4u), x1);
    TF_R(13) TF_R(15) TF_R(26) TF_R(6)
    x0 = MAD1I(one, ks2, x0);        x1 = MAD1I(one, 5u, x1);
#undef TF_R
    return x0 ^ x1;
}

__device__ __forceinline__ float rcp_approx(float a) {
    float r;
    asm("rcp.approx.f32 %0, %1;" : "=f"(r) : "f"(a));
    return r;
}

// One output: argmax over 4 of (x/t + gumbel). Fast path with certified
// bound; precise fallback bit-identical to XLA.
__device__ __forceinline__ float pool_one(float xv0, float xv1, float xv2,
                                          float xv3, float t,
                                          const unsigned* bits) {
    const float xv[4] = {xv0, xv1, xv2, xv3};
    float rcpt = rcp_approx(t);          // t >= 0.1, always normal

    float uu[4], lf[4], ee[4];
#pragma unroll
    for (int k = 0; k < 4; k++) {
        // uniform == XLA exactly: h = bits>>9 (exact), u = rn(h*2^-23 + 1e-20)
        unsigned h = __umulhi(bits[k], 1u << 23);       // IMAD.HI (fma pipe)
        float f = __uint2float_rn(h);                   // exact, h < 2^23
        float u = fmaf(f, 0x1p-23f, 1e-20f);            // single rounding
        uu[k] = u;
        // fast gumbel via MUFU.LG2. True y = -ln(u) >= 5.96e-8 (u <= 1-2^-24),
        // so clamping at 5.9e-8 only fires when the fast y is garbage; then
        // ee blows up and the guard forces the precise fallback (NaN-safe).
        float y = fmaxf(__log2f(u) * -0.69314718056f, 5.9e-8f);
        float g = __log2f(y) * -0.69314718056f;
        float q = xv[k] * rcpt;                         // approx x/t, |q|<10.1
        lf[k] = q + g;
        // certified |fast - precise| bound; constant folds |g|<=16.7 and
        // |q|<10.1 terms with >=2x slack on every component.
        ee[k] = fmaf(2.2e-6f, rcp_approx(y), 4.5e-5f);
    }

    // first-max-wins argmax (matches jnp.argmax tie rule)
    float bl = lf[0], bx = xv[0];
    if (lf[1] > bl) { bl = lf[1]; bx = xv[1]; }
    if (lf[2] > bl) { bl = lf[2]; bx = xv[2]; }
    if (lf[3] > bl) { bl = lf[3]; bx = xv[3]; }

    // guard: winner must beat every rival by more than ee_win + ee_k.
    // Sufficient: only the winner lies within 2*emax of the max.
    float emax = fmaxf(fmaxf(ee[0], ee[1]), fmaxf(ee[2], ee[3]));
    float thr = fmaf(-2.0f, emax, bl);
    int cnt = (lf[0] >= thr) + (lf[1] >= thr) + (lf[2] >= thr) + (lf[3] >= thr);

    if (cnt != 1) {
        // precise path: IEEE div + libdevice logf -- bit-identical to XLA
        float l0 = xv[0] / t + (-logf(-logf(uu[0])));
        float l1 = xv[1] / t + (-logf(-logf(uu[1])));
        float l2 = xv[2] / t + (-logf(-logf(uu[2])));
        float l3 = xv[3] / t + (-logf(-logf(uu[3])));
        float bv = l0; bx = xv[0];
        if (l1 > bv) { bv = l1; bx = xv[1]; }
        if (l2 > bv) { bv = l2; bx = xv[2]; }
        if (l3 > bv) { bv = l3; bx = xv[3]; }
    }
    return bx;
}

// grid (7, C, B), block (28, 8): ho = 8*bx.x + ty, wo pair = 2*tx. No divs.
__global__ __launch_bounds__(224) void tdgs_pool_kernel(
        const float* __restrict__ x,
        const float* __restrict__ temperature,
        float* __restrict__ out,
        unsigned one) {                 // opaque 1 (defeats const-prop)
    int c  = blockIdx.y;
    int b  = blockIdx.z;
    int ho = blockIdx.x * 8 + threadIdx.y;
    int tx = threadIdx.x;               // 0..27, output pair (2tx, 2tx+1)

    int r0 = (c * Ho + ho) * Wo + 2 * tx;          // temp / out row index
    unsigned basec = 4u * ((unsigned)b * (unsigned)P + (unsigned)r0);

    // ---- 8 independent threefry hashes (ILP=8) --------------------------
    unsigned e[8];
    e[0] = MAD1I(one, 42u, basec);
    e[1] = MAD1I(one, 43u, basec);
    e[2] = MAD1I(one, 44u, basec);
    e[3] = MAD1I(one, 45u, basec);
    e[4] = MAD1I(one, 46u, basec);
    e[5] = MAD1I(one, 47u, basec);
    e[6] = MAD1I(one, 48u, basec);
    e[7] = MAD1I(one, 49u, basec);
    unsigned bits[8];
#pragma unroll
    for (int j = 0; j < 8; j++) bits[j] = tf_fold_entry(e[j], one);

    float2 t2 = *reinterpret_cast<const float2*>(temperature + r0);
    float t0 = fmaxf(t2.x, 0.0f) + 0.1f;
    float t1 = fmaxf(t2.y, 0.0f) + 0.1f;

    const float* xp = x + (size_t)b * XPB + (c * H + 2 * ho) * W + 4 * tx;
    float4 row0 = *reinterpret_cast<const float4*>(xp);      // row 2ho
    float4 row1 = *reinterpret_cast<const float4*>(xp + W);  // row 2ho+1

    float o0 = pool_one(row0.x, row0.y, row1.x, row1.y, t0, bits);
    float o1 = pool_one(row0.z, row0.w, row1.z, row1.w, t1, bits + 4);

    *reinterpret_cast<float2*>(out + (size_t)b * P + r0) = make_float2(o0, o1);
}

extern "C" void kernel_launch(void* const* d_in, const int* in_sizes, int n_in,
                              void* d_out, int out_size) {
    const float* x    = (const float*)d_in[0];   // (32,128,112,112) f32
    const float* temp = (const float*)d_in[1];   // (128,56,56) f32
    float* out        = (float*)d_out;           // (32,128,56,56) f32
    (void)in_sizes; (void)n_in; (void)out_size;

    tdgs_pool_kernel<<<dim3(7, C, B), dim3(28, 8)>>>(x, temp, out, 1u);
}

// round 6
// speedup vs baseline: 1.0203x; 1.0203x over previous
#include <cuda_runtime.h>
#include <cstdint>

// ---------------------------------------------------------------------------
// TDGSPooling2d: hard Gumbel-softmax 2x2 pooling (K=2, stride 2).
// out = x[argmax over patch of (x/temp_relu_eps + gumbel)]
// gumbel bits: JAX threefry2x32, key=(0,42), partitionable (bits = o0^o1 of
// threefry(hi=0, lo=flat_index)).
// Threefry adds forced to IMAD (fma pipe) via opaque 'one'; round 1 elided.
// Fast path: MUFU.LG2 gumbel + rcp.approx div with certified error bound and
// NaN-safe clamp; precise (IEEE div + libdevice logf) fallback on unsafe
// margins. 2 outputs/thread; hashes split 4+4 to keep regs <= 32 so 64
// warps/SM are resident (__launch_bounds__(256, 8)).
// ---------------------------------------------------------------------------

constexpr int B  = 32;
constexpr int C  = 128;
constexpr int H  = 112;
constexpr int W  = 112;
constexpr int Ho = 56;
constexpr int Wo = 56;
constexpr int P    = C * Ho * Wo;   // 401408
constexpr int NOUT = B * P;         // 12845056
constexpr int NTHR = NOUT / 2;      // 6422528 == 25088 * 256 (no tail)
constexpr int XPB  = C * H * W;     // 1605632

__device__ __forceinline__ unsigned rotl32(unsigned x, int r) {
    return __funnelshift_l(x, x, r);          // SHF (alu)
}

// d = a*one + c  -> IMAD on the fma pipe ('one' is an opaque runtime 1)
__device__ __forceinline__ unsigned mad1(unsigned a, unsigned one, unsigned c) {
    unsigned d;
    asm("mad.lo.u32 %0, %1, %2, %3;" : "=r"(d) : "r"(a), "r"(one), "r"(c));
    return d;
}
// d = one*imm + c  -> IMAD (imm multiplier) on the fma pipe
#define MAD1I(one, imm, c) ({                                   \
    unsigned d_;                                                \
    asm("mad.lo.u32 %0, %1, %2, %3;"                            \
        : "=r"(d_) : "r"(one), "n"(imm), "r"(c));               \
    d_; })

// Threefry-2x32, 20 rounds, key=(0,42), constants folded, fold o0^o1.
// Entry e must equal counter + 42 (first key injection pre-applied).
// Round 1 elided: initial x0 = 0 so x0_after_add = e.
__device__ __forceinline__ unsigned tf_fold_entry(unsigned e, unsigned one) {
    const unsigned ks1 = 42u;
    const unsigned ks2 = 0x1BD11BDAu ^ 42u;
    unsigned x0 = e;
    unsigned x1 = rotl32(e, 13) ^ e;
#define TF_R(r) { x0 = mad1(x1, one, x0); x1 = rotl32(x1, (r)); x1 ^= x0; }
    TF_R(15) TF_R(26) TF_R(6)
    x0 = MAD1I(one, ks1, x0);        x1 = MAD1I(one, (ks2 + 1u), x1);
    TF_R(17) TF_R(29) TF_R(16) TF_R(24)
    x0 = MAD1I(one, ks2, x0);        x1 = MAD1I(one, 2u, x1);
    TF_R(13) TF_R(15) TF_R(26) TF_R(6)
    /* x0 += 0 */                    x1 = MAD1I(one, (ks1 + 3u), x1);
    TF_R(17) TF_R(29) TF_R(16) TF_R(24)
    x0 = MAD1I(one, ks1, x0);        x1 = MAD1I(one, (ks2 + 4u), x1);
    TF_R(13) TF_R(15) TF_R(26) TF_R(6)
    x0 = MAD1I(one, ks2, x0);        x1 = MAD1I(one, 5u, x1);
#undef TF_R
    return x0 ^ x1;
}

__device__ __forceinline__ float rcp_approx(float a) {
    float r;
    asm("rcp.approx.f32 %0, %1;" : "=f"(r) : "f"(a));
    return r;
}

// One output: 4 hashes + argmax over 4 of (x/t + gumbel).
// Fast path with certified bound; precise fallback bit-identical to XLA.
__device__ __forceinline__ float pool_one(float xv0, float xv1, float xv2,
                                          float xv3, float t,
                                          unsigned ebase, unsigned one) {
    const float xv[4] = {xv0, xv1, xv2, xv3};
    float rcpt = rcp_approx(t);          // t >= 0.1, always normal

    float uu[4], lf[4], ee[4];
#pragma unroll
    for (int k = 0; k < 4; k++) {
        unsigned bits = tf_fold_entry(mad1((unsigned)k, one, ebase), one);
        // uniform == XLA exactly: h = bits>>9 (exact), u = rn(h*2^-23 + 1e-20)
        unsigned h = __umulhi(bits, 1u << 23);          // IMAD.HI (fma pipe)
        float f = __uint2float_rn(h);                   // exact, h < 2^23
        float u = fmaf(f, 0x1p-23f, 1e-20f);            // single rounding
        uu[k] = u;
        // fast gumbel via MUFU.LG2. True y = -ln(u) >= 5.96e-8, so the clamp
        // only fires when fast y is garbage; then ee explodes -> fallback.
        float y = fmaxf(__log2f(u) * -0.69314718056f, 5.9e-8f);
        float g = __log2f(y) * -0.69314718056f;
        float q = xv[k] * rcpt;                         // approx x/t, |q|<10.1
        lf[k] = q + g;
        // certified |fast - precise| bound (constants fold |g|,|q| terms,
        // >=2x slack on every component)
        ee[k] = fmaf(2.2e-6f, rcp_approx(y), 4.5e-5f);
    }

    // first-max-wins argmax (matches jnp.argmax tie rule)
    float bl = lf[0], bx = xv[0];
    if (lf[1] > bl) { bl = lf[1]; bx = xv[1]; }
    if (lf[2] > bl) { bl = lf[2]; bx = xv[2]; }
    if (lf[3] > bl) { bl = lf[3]; bx = xv[3]; }

    // guard: only the winner may lie within 2*emax of the max
    float emax = fmaxf(fmaxf(ee[0], ee[1]), fmaxf(ee[2], ee[3]));
    float thr = fmaf(-2.0f, emax, bl);
    int cnt = (lf[0] >= thr) + (lf[1] >= thr) + (lf[2] >= thr) + (lf[3] >= thr);

    if (cnt != 1) {
        // precise path: IEEE div + libdevice logf -- bit-identical to XLA
        float l0 = xv[0] / t + (-logf(-logf(uu[0])));
        float l1 = xv[1] / t + (-logf(-logf(uu[1])));
        float l2 = xv[2] / t + (-logf(-logf(uu[2])));
        float l3 = xv[3] / t + (-logf(-logf(uu[3])));
        float bv = l0; bx = xv[0];
        if (l1 > bv) { bv = l1; bx = xv[1]; }
        if (l2 > bv) { bv = l2; bx = xv[2]; }
        if (l3 > bv) { bv = l3; bx = xv[3]; }
    }
    return bx;
}

__global__ __launch_bounds__(256, 8) void tdgs_pool_kernel(
        const float* __restrict__ x,
        const float* __restrict__ temperature,
        float* __restrict__ out,
        unsigned one) {                 // opaque 1 (defeats const-prop)
    int idx = blockIdx.x * blockDim.x + threadIdx.x;   // grid exact, no tail
    int tid2 = idx * 2;                 // first of the output pair

    // ---- decode (b,c,ho,wo) for the pair (umulhi-magic divisions) -------
    int b = tid2 / P;
    int r = tid2 - b * P;
    int c = r / (Ho * Wo);
    int s = r - c * (Ho * Wo);
    int ho = s / Wo;
    int wo = s - ho * Wo;               // even

    float2 t2 = *reinterpret_cast<const float2*>(temperature + r);
    float t0 = fmaxf(t2.x, 0.0f) + 0.1f;
    float t1 = fmaxf(t2.y, 0.0f) + 0.1f;

    const float* xp = x + b * XPB + (c * H + 2 * ho) * W + 2 * wo;
    float4 row0 = *reinterpret_cast<const float4*>(xp);      // row 2ho
    float4 row1 = *reinterpret_cast<const float4*>(xp + W);  // row 2ho+1

    // entries: counter + 42 pre-applied; two groups of 4 (low live regs)
    unsigned e0 = MAD1I(one, 42u, 8u * (unsigned)idx);

    float o0 = pool_one(row0.x, row0.y, row1.x, row1.y, t0, e0, one);
    float o1 = pool_one(row0.z, row0.w, row1.z, row1.w, t1,
                        MAD1I(one, 4u, e0), one);

    *reinterpret_cast<float2*>(out + tid2) = make_float2(o0, o1);
}

extern "C" void kernel_launch(void* const* d_in, const int* in_sizes, int n_in,
                              void* d_out, int out_size) {
    const float* x    = (const float*)d_in[0];   // (32,128,112,112) f32
    const float* temp = (const float*)d_in[1];   // (128,56,56) f32
    float* out        = (float*)d_out;           // (32,128,56,56) f32
    (void)in_sizes; (void)n_in; (void)out_size;

    tdgs_pool_kernel<<<NTHR / 256, 256>>>(x, temp, out, 1u);
}

// round 7
// speedup vs baseline: 1.0248x; 1.0044x over previous
#include <cuda_runtime.h>
#include <cstdint>

// ---------------------------------------------------------------------------
// TDGSPooling2d: hard Gumbel-softmax 2x2 pooling (K=2, stride 2).
// out = x[argmax over patch of (x/temp_relu_eps + gumbel)]
// gumbel bits: JAX threefry2x32, key=(0,42), partitionable (bits = o0^o1 of
// threefry(hi=0, lo=flat_index)).
// Pipe balancing:
//  - threefry adds forced to IMAD (fma pipe) via opaque 'one'; round 1 elided
//  - 3 of 19 rotates per hash converted to mul-form (IMAD.LO+IMAD.HI) with
//    the XOR fused into one LOP3 ((lo|hi)^x0, LUT 0x56) -> alu op count drops
//  - uniform built entirely on the fma pipe (umulhi+IMAD+2xFADD, no I2F/SHF)
// Fast path: MUFU.LG2 gumbel + rcp.approx with certified error bound (single
// rcp of ymin) and NaN-safe clamp; precise (IEEE div + libdevice logf)
// fallback on unsafe margins. 2 outputs/thread, regs capped for 8 blocks/SM.
// ---------------------------------------------------------------------------

constexpr int B  = 32;
constexpr int C  = 128;
constexpr int H  = 112;
constexpr int W  = 112;
constexpr int Ho = 56;
constexpr int Wo = 56;
constexpr int P    = C * Ho * Wo;   // 401408
constexpr int NOUT = B * P;         // 12845056
constexpr int NTHR = NOUT / 2;      // 6422528 == 25088 * 256 (no tail)
constexpr int XPB  = C * H * W;     // 1605632

__device__ __forceinline__ unsigned rotl32(unsigned x, int r) {
    return __funnelshift_l(x, x, r);          // SHF (alu)
}

// d = a*one + c  -> IMAD on the fma pipe ('one' is an opaque runtime 1)
__device__ __forceinline__ unsigned mad1(unsigned a, unsigned one, unsigned c) {
    unsigned d;
    asm("mad.lo.u32 %0, %1, %2, %3;" : "=r"(d) : "r"(a), "r"(one), "r"(c));
    return d;
}
// d = one*imm + c  -> IMAD (imm multiplier) on the fma pipe
#define MAD1I(one, imm, c) ({                                   \
    unsigned d_;                                                \
    asm("mad.lo.u32 %0, %1, %2, %3;"                            \
        : "=r"(d_) : "r"(one), "n"(imm), "r"(c));               \
    d_; })

// (lo | hi) ^ c in one LOP3 (LUT: (0xF0|0xCC)^0xAA = 0x56)
__device__ __forceinline__ unsigned or_xor(unsigned lo, unsigned hi, unsigned c) {
    unsigned d;
    asm("lop3.b32 %0, %1, %2, %3, 0x56;" : "=r"(d) : "r"(lo), "r"(hi), "r"(c));
    return d;
}
// lo = a*m (register multiplier -> IMAD, cannot be strength-reduced)
__device__ __forceinline__ unsigned mul_lo(unsigned a, unsigned m) {
    unsigned d;
    asm("mad.lo.u32 %0, %1, %2, %3;" : "=r"(d) : "r"(a), "r"(m), "n"(0));
    return d;
}

struct Po2 { unsigned p29, p16a, p16b; };   // opaque 2^r values

// Threefry-2x32, 20 rounds, key=(0,42), constants folded, fold o0^o1.
// Entry e must equal counter + 42 (first key injection pre-applied).
// Round 1 elided (x0 starts at 0). Three rotates in mul-form (fma pipe).
__device__ __forceinline__ unsigned tf_fold_entry(unsigned e, unsigned one,
                                                  Po2 p) {
    const unsigned ks1 = 42u;
    const unsigned ks2 = 0x1BD11BDAu ^ 42u;
    unsigned x0 = e;
    unsigned x1 = rotl32(e, 13) ^ e;
#define TF_R(r) { x0 = mad1(x1, one, x0); x1 = rotl32(x1, (r)); x1 ^= x0; }
#define TF_RM(pw) { x0 = mad1(x1, one, x0);                      \
    unsigned lo_ = mul_lo(x1, pw);                               \
    unsigned hi_ = __umulhi(x1, pw);                             \
    x1 = or_xor(lo_, hi_, x0); }
    TF_R(15) TF_R(26) TF_R(6)
    x0 = MAD1I(one, ks1, x0);        x1 = MAD1I(one, (ks2 + 1u), x1);
    TF_R(17) TF_RM(p.p29) TF_RM(p.p16a) TF_R(24)
    x0 = MAD1I(one, ks2, x0);        x1 = MAD1I(one, 2u, x1);
    TF_R(13) TF_R(15) TF_R(26) TF_R(6)
    /* x0 += 0 */                    x1 = MAD1I(one, (ks1 + 3u), x1);
    TF_R(17) TF_R(29) TF_RM(p.p16b) TF_R(24)
    x0 = MAD1I(one, ks1, x0);        x1 = MAD1I(one, (ks2 + 4u), x1);
    TF_R(13) TF_R(15) TF_R(26) TF_R(6)
    x0 = MAD1I(one, ks2, x0);        x1 = MAD1I(one, 5u, x1);
#undef TF_R
#undef TF_RM
    return x0 ^ x1;
}

__device__ __forceinline__ float rcp_approx(float a) {
    float r;
    asm("rcp.approx.f32 %0, %1;" : "=f"(r) : "f"(a));
    return r;
}

// One output: 4 hashes + argmax over 4 of (x/t + gumbel).
// Fast path with certified bound; precise fallback bit-identical to XLA.
__device__ __forceinline__ float pool_one(float xv0, float xv1, float xv2,
                                          float xv3, float t,
                                          unsigned ebase, unsigned one,
                                          Po2 p) {
    const float xv[4] = {xv0, xv1, xv2, xv3};
    float rcpt = rcp_approx(t);          // t >= 0.1, always normal

    float uu[4], lf[4], yy[4];
#pragma unroll
    for (int k = 0; k < 4; k++) {
        unsigned bits = tf_fold_entry(mad1((unsigned)k, one, ebase), one, p);
        // uniform == XLA exactly, built on the fma pipe only:
        //   h = bits>>9 (umulhi exact); (1 + h*2^-23) - 1 = h*2^-23 exactly
        //   (Sterbenz); u = rn(h*2^-23 + 1e-20) -- same single rounding.
        unsigned h = __umulhi(bits, 1u << 23);          // IMAD.HI
        unsigned m = MAD1I(one, 0x3F800000u, h);        // IMAD
        float f = __uint_as_float(m) - 1.0f;            // FADD, exact
        float u = f + 1e-20f;                           // FADD, == XLA
        uu[k] = u;
        // fast gumbel via MUFU.LG2. True y = -ln(u) >= 5.96e-8, so the clamp
        // only fires when fast y is garbage; then the bound explodes.
        float y = fmaxf(__log2f(u) * -0.69314718056f, 5.9e-8f);
        yy[k] = y;
        float g = __log2f(y) * -0.69314718056f;
        float q = xv[k] * rcpt;                         // approx x/t, |q|<10.1
        lf[k] = q + g;
    }

    // first-max-wins argmax (matches jnp.argmax tie rule)
    float bl = lf[0], bx = xv[0];
    if (lf[1] > bl) { bl = lf[1]; bx = xv[1]; }
    if (lf[2] > bl) { bl = lf[2]; bx = xv[2]; }
    if (lf[3] > bl) { bl = lf[3]; bx = xv[3]; }

    // certified |fast - precise| bound, monotone in 1/y -> one rcp of ymin
    // covers all four draws (constants fold |g|,|q| terms, >=2x slack).
    float ymin = fminf(fminf(yy[0], yy[1]), fminf(yy[2], yy[3]));
    float emax = fmaf(2.2e-6f, rcp_approx(ymin), 4.5e-5f);
    float thr = fmaf(-2.0f, emax, bl);
    int cnt = (lf[0] >= thr) + (lf[1] >= thr) + (lf[2] >= thr) + (lf[3] >= thr);

    if (cnt != 1) {
        // precise path: IEEE div + libdevice logf -- bit-identical to XLA
        float l0 = xv[0] / t + (-logf(-logf(uu[0])));
        float l1 = xv[1] / t + (-logf(-logf(uu[1])));
        float l2 = xv[2] / t + (-logf(-logf(uu[2])));
        float l3 = xv[3] / t + (-logf(-logf(uu[3])));
        float bv = l0; bx = xv[0];
        if (l1 > bv) { bv = l1; bx = xv[1]; }
        if (l2 > bv) { bv = l2; bx = xv[2]; }
        if (l3 > bv) { bv = l3; bx = xv[3]; }
    }
    return bx;
}

__global__ __launch_bounds__(256, 8) void tdgs_pool_kernel(
        const float* __restrict__ x,
        const float* __restrict__ temperature,
        float* __restrict__ out,
        unsigned one) {                 // opaque 1 (defeats const-prop)
    int idx = blockIdx.x * blockDim.x + threadIdx.x;   // grid exact, no tail
    int tid2 = idx * 2;                 // first of the output pair

    Po2 p;                              // opaque 2^r rotate multipliers
    p.p29  = one << 29;
    p.p16a = one << 16;
    p.p16b = p.p16a;

    // ---- decode (b,c,ho,wo) for the pair (umulhi-magic divisions) -------
    int b = tid2 / P;
    int r = tid2 - b * P;
    int c = r / (Ho * Wo);
    int s = r - c * (Ho * Wo);
    int ho = s / Wo;
    int wo = s - ho * Wo;               // even

    float2 t2 = *reinterpret_cast<const float2*>(temperature + r);
    float t0 = fmaxf(t2.x, 0.0f) + 0.1f;
    float t1 = fmaxf(t2.y, 0.0f) + 0.1f;

    const float* xp = x + b * XPB + (c * H + 2 * ho) * W + 2 * wo;
    float4 row0 = *reinterpret_cast<const float4*>(xp);      // row 2ho
    float4 row1 = *reinterpret_cast<const float4*>(xp + W);  // row 2ho+1

    // entries: counter + 42 pre-applied; two groups of 4 (low live regs)
    unsigned e0 = MAD1I(one, 42u, 8u * (unsigned)idx);

    float o0 = pool_one(row0.x, row0.y, row1.x, row1.y, t0, e0, one, p);
    float o1 = pool_one(row0.z, row0.w, row1.z, row1.w, t1,
                        MAD1I(one, 4u, e0), one, p);

    *reinterpret_cast<float2*>(out + tid2) = make_float2(o0, o1);
}

extern "C" void kernel_launch(void* const* d_in, const int* in_sizes, int n_in,
                              void* d_out, int out_size) {
    const float* x    = (const float*)d_in[0];   // (32,128,112,112) f32
    const float* temp = (const float*)d_in[1];   // (128,56,56) f32
    float* out        = (float*)d_out;           // (32,128,56,56) f32
    (void)in_sizes; (void)n_in; (void)out_size;

    tdgs_pool_kernel<<<NTHR / 256, 256>>>(x, temp, out, 1u);
}

// round 8
// speedup vs baseline: 1.0394x; 1.0143x over previous
#include <cuda_runtime.h>
#include <cstdint>

// ---------------------------------------------------------------------------
// TDGSPooling2d: hard Gumbel-softmax 2x2 pooling (K=2, stride 2).
// out = x[argmax over patch of (x/temp_relu_eps + gumbel)]
// gumbel bits: JAX threefry2x32, key=(0,42), partitionable (bits = o0^o1 of
// threefry(hi=0, lo=flat_index)).
// Pipe balancing: threefry adds forced to IMAD (fma pipe) via opaque 'one';
// round 1 elided; 3 rotates in mul-form (IMAD.LO+IMAD.HI + fused LOP3).
// Fast path scores in the log2 domain: s = x*(rcp(t)*log2e) - log2(z),
// z = max(-log2(u), 8.6e-8)  -- same argmax as l = x/t + gumbel (shared
// constant -log2(ln2) cancels). Certified error bound (single rcp of zmin);
// precise (IEEE div + libdevice logf) fallback on unsafe margins.
// 3D grid (7,C,B) x (28,8): zero integer divisions; 2 outputs/thread;
// __launch_bounds__(224,9) -> regs<=32, 63 warps/SM.
// ---------------------------------------------------------------------------

constexpr int B  = 32;
constexpr int C  = 128;
constexpr int H  = 112;
constexpr int W  = 112;
constexpr int Ho = 56;
constexpr int Wo = 56;
constexpr int P   = C * Ho * Wo;   // 401408
constexpr int XPB = C * H * W;     // 1605632

__device__ __forceinline__ unsigned rotl32(unsigned x, int r) {
    return __funnelshift_l(x, x, r);          // SHF (alu)
}

// d = a*one + c  -> IMAD on the fma pipe ('one' is an opaque runtime 1)
__device__ __forceinline__ unsigned mad1(unsigned a, unsigned one, unsigned c) {
    unsigned d;
    asm("mad.lo.u32 %0, %1, %2, %3;" : "=r"(d) : "r"(a), "r"(one), "r"(c));
    return d;
}
// d = one*imm + c  -> IMAD (imm multiplier) on the fma pipe
#define MAD1I(one, imm, c) ({                                   \
    unsigned d_;                                                \
    asm("mad.lo.u32 %0, %1, %2, %3;"                            \
        : "=r"(d_) : "r"(one), "n"(imm), "r"(c));               \
    d_; })

// (lo | hi) ^ c in one LOP3 (LUT: (0xF0|0xCC)^0xAA = 0x56)
__device__ __forceinline__ unsigned or_xor(unsigned lo, unsigned hi, unsigned c) {
    unsigned d;
    asm("lop3.b32 %0, %1, %2, %3, 0x56;" : "=r"(d) : "r"(lo), "r"(hi), "r"(c));
    return d;
}
// lo = a*m (register multiplier -> IMAD, cannot be strength-reduced)
__device__ __forceinline__ unsigned mul_lo(unsigned a, unsigned m) {
    unsigned d;
    asm("mad.lo.u32 %0, %1, %2, %3;" : "=r"(d) : "r"(a), "r"(m), "n"(0));
    return d;
}

struct Po2 { unsigned p29, p16a, p16b; };   // opaque 2^r values

// Threefry-2x32, 20 rounds, key=(0,42), constants folded, fold o0^o1.
// Entry e must equal counter + 42 (first key injection pre-applied).
// Round 1 elided (x0 starts at 0). Three rotates in mul-form (fma pipe).
__device__ __forceinline__ unsigned tf_fold_entry(unsigned e, unsigned one,
                                                  Po2 p) {
    const unsigned ks1 = 42u;
    const unsigned ks2 = 0x1BD11BDAu ^ 42u;
    unsigned x0 = e;
    unsigned x1 = rotl32(e, 13) ^ e;
#define TF_R(r) { x0 = mad1(x1, one, x0); x1 = rotl32(x1, (r)); x1 ^= x0; }
#define TF_RM(pw) { x0 = mad1(x1, one, x0);                      \
    unsigned lo_ = mul_lo(x1, pw);                               \
    unsigned hi_ = __umulhi(x1, pw);                             \
    x1 = or_xor(lo_, hi_, x0); }
    TF_R(15) TF_R(26) TF_R(6)
    x0 = MAD1I(one, ks1, x0);        x1 = MAD1I(one, (ks2 + 1u), x1);
    TF_R(17) TF_RM(p.p29) TF_RM(p.p16a) TF_R(24)
    x0 = MAD1I(one, ks2, x0);        x1 = MAD1I(one, 2u, x1);
    TF_R(13) TF_R(15) TF_R(26) TF_R(6)
    /* x0 += 0 */                    x1 = MAD1I(one, (ks1 + 3u), x1);
    TF_R(17) TF_R(29) TF_RM(p.p16b) TF_R(24)
    x0 = MAD1I(one, ks1, x0);        x1 = MAD1I(one, (ks2 + 4u), x1);
    TF_R(13) TF_R(15) TF_R(26) TF_R(6)
    x0 = MAD1I(one, ks2, x0);        x1 = MAD1I(one, 5u, x1);
#undef TF_R
#undef TF_RM
    return x0 ^ x1;
}

__device__ __forceinline__ float rcp_approx(float a) {
    float r;
    asm("rcp.approx.f32 %0, %1;" : "=f"(r) : "f"(a));
    return r;
}

// One output: 4 hashes + argmax over 4 of (x/t + gumbel).
// Fast path scores in lg2 domain with certified bound; precise fallback
// bit-identical to XLA.
__device__ __forceinline__ float pool_one(float xv0, float xv1, float xv2,
                                          float xv3, float t,
                                          unsigned ebase, unsigned one,
                                          Po2 p) {
    const float xv[4] = {xv0, xv1, xv2, xv3};
    // s = x * (rcp(t)*log2e) - lg2(z):  one rcp + one FMUL per output
    float rt2 = rcp_approx(t) * 1.44269504f;

    float uu[4], ss[4], zz[4];
#pragma unroll
    for (int k = 0; k < 4; k++) {
        unsigned bits = tf_fold_entry(
            k == 0 ? ebase : mad1((unsigned)k, one, ebase), one, p);
        // uniform == XLA exactly, built on the fma pipe only:
        //   h = bits>>9 (umulhi exact); (1 + h*2^-23) - 1 = h*2^-23 exactly
        //   (Sterbenz); u = rn(h*2^-23 + 1e-20) -- same single rounding.
        unsigned h = __umulhi(bits, 1u << 23);          // IMAD.HI
        unsigned m = MAD1I(one, 0x3F800000u, h);        // IMAD
        float f = __uint_as_float(m) - 1.0f;            // FADD, exact
        float u = f + 1e-20f;                           // FADD, == XLA
        uu[k] = u;
        // z = -lg2(u), clamped (true z >= 2^-24*lg2e; clamp only fires when
        // the MUFU value is garbage near u~1 -> bound explodes -> fallback).
        float z = fmaxf(-__log2f(u), 8.6e-8f);
        zz[k] = z;
        float w = __log2f(z);
        // s_k = l_k/ln2 - lg2(ln2): same argmax as l_k (const cancels)
        ss[k] = fmaf(xv[k], rt2, -w);
    }

    // first-max-wins argmax (matches jnp.argmax tie rule)
    float bl = ss[0], bx = xv[0];
    if (ss[1] > bl) { bl = ss[1]; bx = xv[1]; }
    if (ss[2] > bl) { bl = ss[2]; bx = xv[2]; }
    if (ss[3] > bl) { bl = ss[3]; bx = xv[3]; }

    // certified |fast - precise| bound (s-units), monotone in 1/z -> one rcp
    // of zmin covers all draws; constants fold |x*rt2|<=14.6, |w|<=6.1 terms
    // and the folded-rcpt error with >=2x slack.
    float zmin = fminf(fminf(zz[0], zz[1]), fminf(zz[2], zz[3]));
    float emax = fmaf(1e-5f, rcp_approx(zmin), 2e-4f);
    float thr = fmaf(-2.0f, emax, bl);
    int cnt = (ss[0] >= thr) + (ss[1] >= thr) + (ss[2] >= thr) + (ss[3] >= thr);

    if (cnt != 1) {
        // precise path: IEEE div + libdevice logf -- bit-identical to XLA
        float l0 = xv[0] / t + (-logf(-logf(uu[0])));
        float l1 = xv[1] / t + (-logf(-logf(uu[1])));
        float l2 = xv[2] / t + (-logf(-logf(uu[2])));
        float l3 = xv[3] / t + (-logf(-logf(uu[3])));
        float bv = l0; bx = xv[0];
        if (l1 > bv) { bv = l1; bx = xv[1]; }
        if (l2 > bv) { bv = l2; bx = xv[2]; }
        if (l3 > bv) { bv = l3; bx = xv[3]; }
    }
    return bx;
}

// grid (7, C, B), block (28, 8): ho = 8*bx + ty, wo pair = 2*tx. No divides.
__global__ __launch_bounds__(224, 9) void tdgs_pool_kernel(
        const float* __restrict__ x,
        const float* __restrict__ temperature,
        float* __restrict__ out,
        unsigned one) {                 // opaque 1 (defeats const-prop)
    int c  = blockIdx.y;
    int b  = blockIdx.z;
    int ho = blockIdx.x * 8 + threadIdx.y;
    int tx = threadIdx.x;               // 0..27, output pair (2tx, 2tx+1)

    Po2 p;                              // opaque 2^r rotate multipliers
    p.p29  = one << 29;
    p.p16a = one << 16;
    p.p16b = p.p16a;

    int r0 = (c * Ho + ho) * Wo + 2 * tx;          // temp / out row index
    unsigned basec = 4u * ((unsigned)b * (unsigned)P + (unsigned)r0);

    float2 t2 = *reinterpret_cast<const float2*>(temperature + r0);
    float t0 = fmaxf(t2.x, 0.0f) + 0.1f;
    float t1 = fmaxf(t2.y, 0.0f) + 0.1f;

    const float* xp = x + (size_t)b * XPB + (c * H + 2 * ho) * W + 4 * tx;
    float4 row0 = *reinterpret_cast<const float4*>(xp);      // row 2ho
    float4 row1 = *reinterpret_cast<const float4*>(xp + W);  // row 2ho+1

    // entries: counter + 42 pre-applied; two groups of 4 (low live regs)
    unsigned e0 = MAD1I(one, 42u, basec);

    float o0 = pool_one(row0.x, row0.y, row1.x, row1.y, t0, e0, one, p);
    float o1 = pool_one(row0.z, row0.w, row1.z, row1.w, t1,
                        MAD1I(one, 4u, e0), one, p);

    *reinterpret_cast<float2*>(out + (size_t)b * P + r0) = make_float2(o0, o1);
}

extern "C" void kernel_launch(void* const* d_in, const int* in_sizes, int n_in,
                              void* d_out, int out_size) {
    const float* x    = (const float*)d_in[0];   // (32,128,112,112) f32
    const float* temp = (const float*)d_in[1];   // (128,56,56) f32
    float* out        = (float*)d_out;           // (32,128,56,56) f32
    (void)in_sizes; (void)n_in; (void)out_size;

    tdgs_pool_kernel<<<dim3(7, C, B), dim3(28, 8)>>>(x, temp, out, 1u);
}